// round 16
// baseline (speedup 1.0000x reference)
#include <cuda_runtime.h>
#include <cuda_bf16.h>
#include <cstdint>
#include <cmath>

// Problem constants
#define LQ    512   // sequence length
#define BQ    64    // batch
#define DQ    512   // input dim
#define HALFQ 256   // hidden per direction
#define GATES 1024  // 4*HALF

// ---------------------------------------------------------------------------
// Scratch (layouts validated R8-R15)
// ---------------------------------------------------------------------------
__device__ __align__(16) float         g_xw[2ull * 512 * 8 * 8 * 8 * 128];
__device__ __align__(16) __nv_bfloat16 g_xhi[32768ull * 512];
__device__ __align__(16) __nv_bfloat16 g_xlo[32768ull * 512];
__device__ __align__(16) __nv_bfloat16 g_whi[2048ull * 512];
__device__ __align__(16) __nv_bfloat16 g_wlo[2048ull * 512];
__device__ __align__(16) float         g_bsum[2048];

// ---------------------------------------------------------------------------
// Helpers
// ---------------------------------------------------------------------------
__device__ __forceinline__ uint32_t smem_u32(const void* p) {
    uint32_t a;
    asm("{ .reg .u64 t; cvta.to.shared.u64 t, %1; cvt.u32.u64 %0, t; }"
        : "=r"(a) : "l"(p));
    return a;
}
__device__ __forceinline__ uint32_t ctarank() {
    uint32_t r;
    asm("mov.u32 %0, %%cluster_ctarank;" : "=r"(r));
    return r;
}
__device__ __forceinline__ void cp16(uint32_t dst, const void* src) {
    asm volatile("cp.async.cg.shared.global [%0], [%1], 16;"
                 :: "r"(dst), "l"(src) : "memory");
}
__device__ __forceinline__ void cp_commit() {
    asm volatile("cp.async.commit_group;" ::: "memory");
}
template <int N>
__device__ __forceinline__ void cp_wait() {
    asm volatile("cp.async.wait_group %0;" :: "n"(N) : "memory");
}
__device__ __forceinline__ void ldm_x4(uint32_t& r0, uint32_t& r1,
                                       uint32_t& r2, uint32_t& r3, uint32_t a) {
    asm volatile("ldmatrix.sync.aligned.m8n8.x4.shared.b16 {%0,%1,%2,%3}, [%4];"
                 : "=r"(r0), "=r"(r1), "=r"(r2), "=r"(r3) : "r"(a));
}
__device__ __forceinline__ void mma_bf16(float* c, const uint32_t* a,
                                         uint32_t b0, uint32_t b1) {
    asm volatile("mma.sync.aligned.m16n8k16.row.col.f32.bf16.bf16.f32 "
                 "{%0,%1,%2,%3}, {%4,%5,%6,%7}, {%8,%9}, {%0,%1,%2,%3};"
                 : "+f"(c[0]), "+f"(c[1]), "+f"(c[2]), "+f"(c[3])
                 : "r"(a[0]), "r"(a[1]), "r"(a[2]), "r"(a[3]),
                   "r"(b0), "r"(b1));
}
// accurate activations via MUFU exp (error ~1e-6; validated R8/R11-R15)
__device__ __forceinline__ float sigm_e(float x) {
    return __fdividef(1.f, 1.f + __expf(-x));
}
__device__ __forceinline__ float tanh_e(float x) {
    return 1.f - __fdividef(2.f, __expf(2.f * x) + 1.f);
}
__device__ __forceinline__ uint32_t pack_bf16(float a, float b) {
    return (uint32_t)__bfloat16_as_ushort(__float2bfloat16(a)) |
           ((uint32_t)__bfloat16_as_ushort(__float2bfloat16(b)) << 16);
}

// ===========================================================================
// Kernel 0a: split x into hi/lo bf16
// ===========================================================================
__global__ __launch_bounds__(256)
void conv_x(const float* __restrict__ x)
{
    size_t i = ((size_t)blockIdx.x * 256 + threadIdx.x) * 4;
    float4 v = *(const float4*)(x + i);
    float vv[4] = {v.x, v.y, v.z, v.w};
    unsigned short hi[4], lo[4];
#pragma unroll
    for (int j = 0; j < 4; j++) {
        __nv_bfloat16 h = __float2bfloat16(vv[j]);
        __nv_bfloat16 l = __float2bfloat16(vv[j] - __bfloat162float(h));
        hi[j] = __bfloat16_as_ushort(h);
        lo[j] = __bfloat16_as_ushort(l);
    }
    *(uint2*)((unsigned short*)g_xhi + i) = *(uint2*)hi;
    *(uint2*)((unsigned short*)g_xlo + i) = *(uint2*)lo;
}

// ===========================================================================
// Kernel 0b: split W into hi/lo bf16 (concat fwd|bwd), and combined biases
// ===========================================================================
__global__ __launch_bounds__(256)
void conv_w(const float* __restrict__ Wf, const float* __restrict__ Wb,
            const float* __restrict__ bihf, const float* __restrict__ bhhf,
            const float* __restrict__ bihb, const float* __restrict__ bhhb)
{
    size_t e0 = ((size_t)blockIdx.x * 256 + threadIdx.x) * 4;
    int row = (int)(e0 >> 9);
    int col = (int)(e0 & 511);
    const float* src = (row < GATES) ? (Wf + (size_t)row * 512 + col)
                                     : (Wb + (size_t)(row - GATES) * 512 + col);
    float4 v = *(const float4*)src;
    float vv[4] = {v.x, v.y, v.z, v.w};
    unsigned short hi[4], lo[4];
#pragma unroll
    for (int j = 0; j < 4; j++) {
        __nv_bfloat16 h = __float2bfloat16(vv[j]);
        __nv_bfloat16 l = __float2bfloat16(vv[j] - __bfloat162float(h));
        hi[j] = __bfloat16_as_ushort(h);
        lo[j] = __bfloat16_as_ushort(l);
    }
    *(uint2*)((unsigned short*)g_whi + e0) = *(uint2*)hi;
    *(uint2*)((unsigned short*)g_wlo + e0) = *(uint2*)lo;

    if (blockIdx.x == 0) {
        for (int n = threadIdx.x; n < 2048; n += 256) {
            int r = n & (GATES - 1);
            g_bsum[n] = (n < GATES) ? (bihf[r] + bhhf[r]) : (bihb[r] + bhhb[r]);
        }
    }
}

// ===========================================================================
// Kernel 1: mma.sync bf16 GEMM  C[32768,2048] = x @ Wcat^T + bsum
// (unchanged — validated R8/R11-R15, rel_err 6e-6)
// ===========================================================================
#define STG_HALF 20480                      // halves per stage (4 * 128*40)
#define GEMM_SMEM (3 * STG_HALF * 2)        // 122880 bytes

__device__ __forceinline__ void stage_load(uint32_t smbase, int st,
                                           int m0, int n0, int k0, int tid)
{
    const __nv_bfloat16* const xh = g_xhi + (size_t)m0 * 512 + k0;
    const __nv_bfloat16* const xl = g_xlo + (size_t)m0 * 512 + k0;
    const __nv_bfloat16* const wh = g_whi + (size_t)n0 * 512 + k0;
    const __nv_bfloat16* const wl = g_wlo + (size_t)n0 * 512 + k0;
    const uint32_t sbase = smbase + st * (STG_HALF * 2);
    const int r0  = tid >> 2;          // 0..63
    const int seg = tid & 3;           // 0..3

#pragma unroll
    for (int mat = 0; mat < 4; mat++) {
        const __nv_bfloat16* src =
            (mat == 0) ? xh : (mat == 1) ? xl : (mat == 2) ? wh : wl;
#pragma unroll
        for (int hh = 0; hh < 2; hh++) {
            int row = r0 + hh * 64;
            uint32_t dst = sbase + (uint32_t)(mat * 10240 + row * 80 + seg * 16);
            cp16(dst, src + (size_t)row * 512 + seg * 8);
        }
    }
}

__global__ __launch_bounds__(256)
void lstm_gemm_mma()
{
    extern __shared__ char smg[];
    const uint32_t smbase = smem_u32(smg);
    const int tid  = threadIdx.x;
    const int lane = tid & 31;
    const int wid  = tid >> 5;
    const int wm = (wid & 3) * 32;          // warp m offset
    const int wn = (wid >> 2) * 64;         // warp n offset
    const int n0 = blockIdx.x * 128;        // 16 n-tiles (fast -> x reuse in L2)
    const int m0 = blockIdx.y * 128;        // 256 m-tiles

    float acc[2][8][4];
#pragma unroll
    for (int i = 0; i < 2; i++)
#pragma unroll
        for (int j = 0; j < 8; j++)
#pragma unroll
            for (int q = 0; q < 4; q++) acc[i][j][q] = 0.f;

    const uint32_t a_row = (uint32_t)(lane & 15);
    const uint32_t a_col = (uint32_t)((lane >> 4) * 8);
    const uint32_t b_row = (uint32_t)((lane & 7) + ((lane >> 4) << 3));
    const uint32_t b_col = (uint32_t)(((lane >> 3) & 1) * 8);

    stage_load(smbase, 0, m0, n0, 0, tid);  cp_commit();
    stage_load(smbase, 1, m0, n0, 32, tid); cp_commit();

    for (int c = 0; c < 16; c++) {
        if (c + 2 < 16) stage_load(smbase, (c + 2) % 3, m0, n0, (c + 2) * 32, tid);
        cp_commit();
        cp_wait<2>();
        __syncthreads();

        uint32_t sb  = smbase + (uint32_t)((c % 3) * (STG_HALF * 2));
        uint32_t sAh = sb;
        uint32_t sAl = sb + 10240;
        uint32_t sBh = sb + 20480;
        uint32_t sBl = sb + 30720;

#pragma unroll
        for (int kk = 0; kk < 2; kk++) {
            const uint32_t kb = (uint32_t)(kk * 32);

            uint32_t ah[2][4], al[2][4];
#pragma unroll
            for (int tm = 0; tm < 2; tm++) {
                uint32_t roff = (uint32_t)(wm + tm * 16) + a_row;
                uint32_t off = roff * 80 + kb + a_col * 2;
                ldm_x4(ah[tm][0], ah[tm][1], ah[tm][2], ah[tm][3], sAh + off);
                ldm_x4(al[tm][0], al[tm][1], al[tm][2], al[tm][3], sAl + off);
            }

            uint32_t b[16];
#pragma unroll
            for (int p = 0; p < 4; p++) {
                uint32_t roff = (uint32_t)(wn + p * 16) + b_row;
                uint32_t off = roff * 80 + kb + b_col * 2;
                ldm_x4(b[p * 4 + 0], b[p * 4 + 1], b[p * 4 + 2], b[p * 4 + 3],
                       sBh + off);
            }
#pragma unroll
            for (int tm = 0; tm < 2; tm++)
#pragma unroll
                for (int tn = 0; tn < 8; tn++) {
                    mma_bf16(acc[tm][tn], ah[tm], b[tn * 2], b[tn * 2 + 1]);
                    mma_bf16(acc[tm][tn], al[tm], b[tn * 2], b[tn * 2 + 1]);
                }
#pragma unroll
            for (int p = 0; p < 4; p++) {
                uint32_t roff = (uint32_t)(wn + p * 16) + b_row;
                uint32_t off = roff * 80 + kb + b_col * 2;
                ldm_x4(b[p * 4 + 0], b[p * 4 + 1], b[p * 4 + 2], b[p * 4 + 3],
                       sBl + off);
            }
#pragma unroll
            for (int tm = 0; tm < 2; tm++)
#pragma unroll
                for (int tn = 0; tn < 8; tn++)
                    mma_bf16(acc[tm][tn], ah[tm], b[tn * 2], b[tn * 2 + 1]);
        }
        __syncthreads();
    }

#pragma unroll
    for (int tm = 0; tm < 2; tm++) {
#pragma unroll
        for (int tn = 0; tn < 8; tn++) {
            const int n    = n0 + wn + tn * 8 + (lane & 3) * 2;
            const int dir  = n >> 10;
            const int rowg = n & (GATES - 1);
            const int gate = rowg >> 8;
            const int slc  = (rowg >> 5) & 7;
            const int j    = rowg & 31;
            float b0 = g_bsum[n];
            float b1 = g_bsum[n + 1];
#pragma unroll
            for (int rr = 0; rr < 2; rr++) {
                const int m  = m0 + wm + tm * 16 + (lane >> 2) + rr * 8;
                const int t  = m >> 6;
                const int bq = m & 63;
                size_t base = (((((size_t)dir * LQ + t) * 8 + (bq >> 3)) * 8 + slc) * 8
                               + (bq & 7)) * 128 + gate * 32 + j;
                float2 v;
                v.x = acc[tm][tn][rr * 2 + 0] + b0;
                v.y = acc[tm][tn][rr * 2 + 1] + b1;
                *(float2*)&g_xw[base] = v;
            }
        }
    }
}

// ===========================================================================
// Kernel 2: recurrence via HMMA. Cluster of 8 CTAs.
// R16: each cluster runs FOUR batch-groups (32 batches = a direction half)
// per step under ONE cluster barrier — fixed sync cost amortized over 4
// chains (R15 validated this lever at 2 chains). 32 CTAs x 512 thr.
// Per warp/step: 96 MMAs over 4 n8-tile accumulators; activation threads
// own 2 batches each (2 cell states). xW staged via cp.async double buffer.
// ===========================================================================
#define HPITCH   264                         // halves per h row (pad: 528B)
#define R_SH_HI  0                           // [2][32][HPITCH] bf16  (33792 B)
#define R_SH_LO  33792                       // [2][32][HPITCH] bf16
#define R_GTP    67584                       // [2][32][132] float    (33792 B)
#define R_XWS    101376                      // [2][32*128] float     (32768 B)
#define REC_SMEM 134144

__global__ void __cluster_dims__(8, 1, 1) __launch_bounds__(512, 1)
lstm_recurrence(const float* __restrict__ Whh_f,
                const float* __restrict__ Whh_b,
                const float* __restrict__ mask,
                float* __restrict__ out)
{
    extern __shared__ char smr[];
    float* gtp = (float*)(smr + R_GTP);      // [(kh*32 + b)*132 + r]
    float* xws = (float*)(smr + R_XWS);      // [p*4096 + b*128 + g*32 + j]

    const int tid  = threadIdx.x;
    const int lane = tid & 31;
    const int w    = tid >> 5;               // 0..15
    const int rs   = w >> 1;                 // row slab (16 rows of 128)
    const int kh   = w & 1;                  // k half (128 of 256)
    const uint32_t s = ctarank();            // cluster rank = h-slice
    const int gid = blockIdx.x >> 3;         // 0..3
    const int dir = gid >> 1;                // 0 fwd, 1 bwd
    const int bq4 = gid & 1;                 // which 32-batch half

    const float* Whh = dir ? Whh_b : Whh_f;

    // ---- load W_hh slice into mma A-fragments (split bf16 hi/lo), once ----
    const int r0 = 16 * rs + (lane >> 2);
    const int r1 = r0 + 8;
    const int grow0 = ((r0 >> 5) << 8) | ((int)s << 5) | (r0 & 31);
    const int grow1 = ((r1 >> 5) << 8) | ((int)s << 5) | (r1 & 31);
    const int kc = (lane & 3) * 2;

    uint32_t ahi[8][4], alo[8][4];
#pragma unroll
    for (int kt = 0; kt < 8; kt++) {
        const int kb = kh * 128 + kt * 16 + kc;
#pragma unroll
        for (int q = 0; q < 4; q++) {
            const int gr = (q & 1) ? grow1 : grow0;
            const int kk = kb + ((q >> 1) ? 8 : 0);
            float2 f = *(const float2*)&Whh[(size_t)gr * 256 + kk];
            float hx = __bfloat162float(__float2bfloat16(f.x));
            float hy = __bfloat162float(__float2bfloat16(f.y));
            ahi[kt][q] = pack_bf16(f.x, f.y);
            alo[kt][q] = pack_bf16(f.x - hx, f.y - hy);
        }
    }

    // zero phase-0 h buffers; phase 1 fully overwritten by stores
    {
        __nv_bfloat16* zh = (__nv_bfloat16*)(smr + R_SH_HI);
        __nv_bfloat16* zl = (__nv_bfloat16*)(smr + R_SH_LO);
        for (int idx = tid; idx < 32 * HPITCH; idx += 512) {
            zh[idx] = __float2bfloat16(0.f);
            zl[idx] = __float2bfloat16(0.f);
        }
    }
    __syncthreads();

    const uint32_t hbase  = smem_u32(smr) + R_SH_HI;
    const uint32_t lo_off = R_SH_LO - R_SH_HI;
    const uint32_t tile_off = (uint32_t)(16 * HPITCH * 2);   // batches 16-31
    // B-fragment ldmatrix addressing (validated pattern)
    const uint32_t b_row  = (uint32_t)((lane & 7) + ((lane >> 4) << 3));
    const uint32_t ldm_off = b_row * (HPITCH * 2)
                           + (((lane >> 3) & 1) * 16)
                           + (uint32_t)kh * 256;
    const uint32_t phase_sz = (uint32_t)(32 * HPITCH * 2);

    // activation role: each thread owns batches w and w+16, h-index lane
    const int ab = w;                        // 0..15
    const int aj = lane;
    const int bg0 = bq4 * 32 + ab;           // global batch (first)
    const int bg1 = bg0 + 16;                // global batch (second)
    const int bcol = (lane & 3) * 2;

    // cp.async role: thread fetches 16B of xW for each of its 2 batches
    const int cg  = lane >> 3;               // gate 0..3
    const int cgr = lane & 7;                // 4-float group
    const float* xw_src0 = g_xw
        + ((size_t)dir * LQ * 64 + (size_t)(bg0 >> 3) * 8 + s) * 1024
        + (size_t)(bg0 & 7) * 128 + cg * 32 + cgr * 4;
    const float* xw_src1 = g_xw
        + ((size_t)dir * LQ * 64 + (size_t)(bg1 >> 3) * 8 + s) * 1024
        + (size_t)(bg1 & 7) * 128 + cg * 32 + cgr * 4;
    const uint32_t xw_dst0 = smem_u32(smr) + R_XWS
        + (uint32_t)(ab * 128 + cg * 32 + cgr * 4) * 4;
    const uint32_t xw_dst1 = xw_dst0 + 16 * 128 * 4;

    // DSMEM group offsets for this lane-group's packed h (2 batches)
    const uint32_t grp_hoff0 = (uint32_t)(ab * (HPITCH * 2)
                                          + ((int)s * 32 + (aj & ~3)) * 2);
    const uint32_t grp_hoff1 = grp_hoff0 + tile_off;

    float c0 = 0.f, c1 = 0.f;

#pragma unroll 1
    for (int step = 0; step < LQ; step++) {
        const int t = dir ? (LQ - 1 - step) : step;
        const int p = step & 1;

        // ---- prefetch xW into smem stage + masks (before the wait) ----
        cp16(xw_dst0 + (uint32_t)p * 16384, xw_src0 + (size_t)t * 65536);
        cp16(xw_dst1 + (uint32_t)p * 16384, xw_src1 + (size_t)t * 65536);
        cp_commit();
        float m0 = __ldg(&mask[t * BQ + bg0]);
        float m1 = __ldg(&mask[t * BQ + bg1]);

        if (step > 0)
            asm volatile("barrier.cluster.wait.aligned;" ::: "memory");

        // ---- matvec: this warp's k-half, n=32 (four n8 tiles) ----
        float acc[4][4];
#pragma unroll
        for (int i = 0; i < 4; i++)
#pragma unroll
            for (int q = 0; q < 4; q++) acc[i][q] = 0.f;

        const uint32_t hb = hbase + (uint32_t)p * phase_sz + ldm_off;
#pragma unroll
        for (int kt = 0; kt < 8; kt++) {
            uint32_t bh0, bh1, bh2, bh3, bh4, bh5, bh6, bh7;
            uint32_t bl0, bl1, bl2, bl3, bl4, bl5, bl6, bl7;
            ldm_x4(bh0, bh1, bh2, bh3, hb + kt * 32);
            ldm_x4(bh4, bh5, bh6, bh7, hb + tile_off + kt * 32);
            ldm_x4(bl0, bl1, bl2, bl3, hb + lo_off + kt * 32);
            ldm_x4(bl4, bl5, bl6, bl7, hb + lo_off + tile_off + kt * 32);
            mma_bf16(acc[0], ahi[kt], bh0, bh1);
            mma_bf16(acc[1], ahi[kt], bh2, bh3);
            mma_bf16(acc[2], ahi[kt], bh4, bh5);
            mma_bf16(acc[3], ahi[kt], bh6, bh7);
            mma_bf16(acc[0], ahi[kt], bl0, bl1);
            mma_bf16(acc[1], ahi[kt], bl2, bl3);
            mma_bf16(acc[2], ahi[kt], bl4, bl5);
            mma_bf16(acc[3], ahi[kt], bl6, bl7);
            mma_bf16(acc[0], alo[kt], bh0, bh1);
            mma_bf16(acc[1], alo[kt], bh2, bh3);
            mma_bf16(acc[2], alo[kt], bh4, bh5);
            mma_bf16(acc[3], alo[kt], bh6, bh7);
        }

        // ---- partial gates to smem (per k-half plane, 32 batches) ----
#pragma unroll
        for (int i = 0; i < 4; i++) {
            const int bidx = kh * 32 + i * 8 + bcol;
            gtp[bidx * 132 + r0]       = acc[i][0];
            gtp[(bidx + 1) * 132 + r0] = acc[i][1];
            gtp[bidx * 132 + r1]       = acc[i][2];
            gtp[(bidx + 1) * 132 + r1] = acc[i][3];
        }
        cp_wait<0>();
        __syncthreads();

        // ---- activations: 2 batches per thread ----
        const float* xwp0 = xws + p * 4096 + ab * 128;
        const float* xwp1 = xwp0 + 16 * 128;
        float hv0, hv1;
        {
            float gi = gtp[ab * 132 + aj]      + gtp[(32 + ab) * 132 + aj]      + xwp0[aj];
            float gf = gtp[ab * 132 + 32 + aj] + gtp[(32 + ab) * 132 + 32 + aj] + xwp0[32 + aj];
            float gg = gtp[ab * 132 + 64 + aj] + gtp[(32 + ab) * 132 + 64 + aj] + xwp0[64 + aj];
            float go = gtp[ab * 132 + 96 + aj] + gtp[(32 + ab) * 132 + 96 + aj] + xwp0[96 + aj];
            float i_ = sigm_e(gi), f_ = sigm_e(gf), g_ = tanh_e(gg), o_ = sigm_e(go);
            c0 = f_ * c0 + i_ * g_;
            hv0 = o_ * tanh_e(c0);
            hv0 *= m0; c0 *= m0;
        }
        {
            const int ab1 = 16 + ab;
            float gi = gtp[ab1 * 132 + aj]      + gtp[(32 + ab1) * 132 + aj]      + xwp1[aj];
            float gf = gtp[ab1 * 132 + 32 + aj] + gtp[(32 + ab1) * 132 + 32 + aj] + xwp1[32 + aj];
            float gg = gtp[ab1 * 132 + 64 + aj] + gtp[(32 + ab1) * 132 + 64 + aj] + xwp1[64 + aj];
            float go = gtp[ab1 * 132 + 96 + aj] + gtp[(32 + ab1) * 132 + 96 + aj] + xwp1[96 + aj];
            float i_ = sigm_e(gi), f_ = sigm_e(gf), g_ = tanh_e(gg), o_ = sigm_e(go);
            c1 = f_ * c1 + i_ * g_;
            hv1 = o_ * tanh_e(c1);
            hv1 *= m1; c1 *= m1;
        }

        unsigned short h0hi = __bfloat16_as_ushort(__float2bfloat16(hv0));
        unsigned short h0lo = __bfloat16_as_ushort(
            __float2bfloat16(hv0 - __bfloat162float(__ushort_as_bfloat16(h0hi))));
        unsigned short h1hi = __bfloat16_as_ushort(__float2bfloat16(hv1));
        unsigned short h1lo = __bfloat16_as_ushort(
            __float2bfloat16(hv1 - __bfloat162float(__ushort_as_bfloat16(h1hi))));

        if (step < LQ - 1) {
            // pack 4 lanes' hi/lo into 8B words per batch; leaders store
            uint32_t vh0 = h0hi, vl0 = h0lo, vh1 = h1hi, vl1 = h1lo;
            uint32_t a1 = __shfl_down_sync(0xFFFFFFFFu, vh0, 1);
            uint32_t a2 = __shfl_down_sync(0xFFFFFFFFu, vh0, 2);
            uint32_t a3 = __shfl_down_sync(0xFFFFFFFFu, vh0, 3);
            uint32_t b1_ = __shfl_down_sync(0xFFFFFFFFu, vl0, 1);
            uint32_t b2 = __shfl_down_sync(0xFFFFFFFFu, vl0, 2);
            uint32_t b3 = __shfl_down_sync(0xFFFFFFFFu, vl0, 3);
            uint32_t c1_ = __shfl_down_sync(0xFFFFFFFFu, vh1, 1);
            uint32_t c2 = __shfl_down_sync(0xFFFFFFFFu, vh1, 2);
            uint32_t c3 = __shfl_down_sync(0xFFFFFFFFu, vh1, 3);
            uint32_t d1 = __shfl_down_sync(0xFFFFFFFFu, vl1, 1);
            uint32_t d2 = __shfl_down_sync(0xFFFFFFFFu, vl1, 2);
            uint32_t d3 = __shfl_down_sync(0xFFFFFFFFu, vl1, 3);
            if ((aj & 3) == 0) {
                uint64_t hq0 = (uint64_t)(vh0 | (a1 << 16))
                             | ((uint64_t)(a2 | (a3 << 16)) << 32);
                uint64_t lq0 = (uint64_t)(vl0 | (b1_ << 16))
                             | ((uint64_t)(b2 | (b3 << 16)) << 32);
                uint64_t hq1 = (uint64_t)(vh1 | (c1_ << 16))
                             | ((uint64_t)(c2 | (c3 << 16)) << 32);
                uint64_t lq1 = (uint64_t)(vl1 | (d1 << 16))
                             | ((uint64_t)(d2 | (d3 << 16)) << 32);
                uint32_t la0 = hbase + (uint32_t)(p ^ 1) * phase_sz + grp_hoff0;
#pragma unroll
                for (int rk = 0; rk < 8; rk++) {
                    uint32_t ra;
                    asm volatile("mapa.shared::cluster.u32 %0, %1, %2;"
                                 : "=r"(ra) : "r"(la0), "r"(rk));
                    asm volatile("st.shared::cluster.b64 [%0], %1;"
                                 :: "r"(ra), "l"(hq0) : "memory");
                    asm volatile("st.shared::cluster.b64 [%0], %1;"
                                 :: "r"(ra + lo_off), "l"(lq0) : "memory");
                    asm volatile("st.shared::cluster.b64 [%0], %1;"
                                 :: "r"(ra + tile_off), "l"(hq1) : "memory");
                    asm volatile("st.shared::cluster.b64 [%0], %1;"
                                 :: "r"(ra + tile_off + lo_off), "l"(lq1) : "memory");
                }
            }
            asm volatile("barrier.cluster.arrive.aligned;" ::: "memory");
        }

        // out[] stores AFTER the broadcast/arrive — off the critical path
        out[((size_t)t * BQ + bg0) * (2 * HALFQ) + dir * HALFQ + s * 32 + aj] = hv0;
        out[((size_t)t * BQ + bg1) * (2 * HALFQ) + dir * HALFQ + s * 32 + aj] = hv1;
    }
}

// ===========================================================================
// Launch
// Inputs (metadata order): x, mask, W_ih_f, W_hh_f, b_ih_f, b_hh_f,
//                          W_ih_b, W_hh_b, b_ih_b, b_hh_b
// Output: float32 (L, B, 2*HALF)
// ===========================================================================
extern "C" void kernel_launch(void* const* d_in, const int* in_sizes, int n_in,
                              void* d_out, int out_size)
{
    const float* x     = (const float*)d_in[0];
    const float* mask  = (const float*)d_in[1];
    const float* Wihf  = (const float*)d_in[2];
    const float* Whhf  = (const float*)d_in[3];
    const float* bihf  = (const float*)d_in[4];
    const float* bhhf  = (const float*)d_in[5];
    const float* Wihb  = (const float*)d_in[6];
    const float* Whhb  = (const float*)d_in[7];
    const float* bihb  = (const float*)d_in[8];
    const float* bhhb  = (const float*)d_in[9];
    float* out = (float*)d_out;

    // Phase 0: split-bf16 conversions + bias fold
    conv_x<<<16384, 256>>>(x);
    conv_w<<<1024, 256>>>(Wihf, Wihb, bihf, bhhf, bihb, bhhb);

    // Phase 1: tensor-core (HMMA) input projection into permuted scratch
    cudaFuncSetAttribute(lstm_gemm_mma,
                         cudaFuncAttributeMaxDynamicSharedMemorySize, GEMM_SMEM);
    dim3 ggrid(16, 256);   // n-tiles fast -> x tile reuse in L2
    lstm_gemm_mma<<<ggrid, 256, GEMM_SMEM>>>();

    // Phase 2: recurrence — 32 CTAs x 512 thr, 4 clusters, 4 chains/cluster
    cudaFuncSetAttribute(lstm_recurrence,
                         cudaFuncAttributeMaxDynamicSharedMemorySize, REC_SMEM);
    lstm_recurrence<<<32, 512, REC_SMEM>>>(Whhf, Whhb, mask, out);
}

// round 17
// speedup vs baseline: 1.5384x; 1.5384x over previous
#include <cuda_runtime.h>
#include <cuda_bf16.h>
#include <cstdint>
#include <cmath>

// Problem constants
#define LQ    512   // sequence length
#define BQ    64    // batch
#define DQ    512   // input dim
#define HALFQ 256   // hidden per direction
#define GATES 1024  // 4*HALF

// ---------------------------------------------------------------------------
// Scratch (layouts validated R8-R15)
// ---------------------------------------------------------------------------
__device__ __align__(16) float         g_xw[2ull * 512 * 8 * 8 * 8 * 128];
__device__ __align__(16) __nv_bfloat16 g_xhi[32768ull * 512];
__device__ __align__(16) __nv_bfloat16 g_xlo[32768ull * 512];
__device__ __align__(16) __nv_bfloat16 g_whi[2048ull * 512];
__device__ __align__(16) __nv_bfloat16 g_wlo[2048ull * 512];
__device__ __align__(16) float         g_bsum[2048];

// ---------------------------------------------------------------------------
// Helpers
// ---------------------------------------------------------------------------
__device__ __forceinline__ uint32_t smem_u32(const void* p) {
    uint32_t a;
    asm("{ .reg .u64 t; cvta.to.shared.u64 t, %1; cvt.u32.u64 %0, t; }"
        : "=r"(a) : "l"(p));
    return a;
}
__device__ __forceinline__ uint32_t ctarank() {
    uint32_t r;
    asm("mov.u32 %0, %%cluster_ctarank;" : "=r"(r));
    return r;
}
__device__ __forceinline__ void cp16(uint32_t dst, const void* src) {
    asm volatile("cp.async.cg.shared.global [%0], [%1], 16;"
                 :: "r"(dst), "l"(src) : "memory");
}
__device__ __forceinline__ void cp_commit() {
    asm volatile("cp.async.commit_group;" ::: "memory");
}
template <int N>
__device__ __forceinline__ void cp_wait() {
    asm volatile("cp.async.wait_group %0;" :: "n"(N) : "memory");
}
__device__ __forceinline__ void ldm_x4(uint32_t& r0, uint32_t& r1,
                                       uint32_t& r2, uint32_t& r3, uint32_t a) {
    asm volatile("ldmatrix.sync.aligned.m8n8.x4.shared.b16 {%0,%1,%2,%3}, [%4];"
                 : "=r"(r0), "=r"(r1), "=r"(r2), "=r"(r3) : "r"(a));
}
__device__ __forceinline__ void mma_bf16(float* c, const uint32_t* a,
                                         uint32_t b0, uint32_t b1) {
    asm volatile("mma.sync.aligned.m16n8k16.row.col.f32.bf16.bf16.f32 "
                 "{%0,%1,%2,%3}, {%4,%5,%6,%7}, {%8,%9}, {%0,%1,%2,%3};"
                 : "+f"(c[0]), "+f"(c[1]), "+f"(c[2]), "+f"(c[3])
                 : "r"(a[0]), "r"(a[1]), "r"(a[2]), "r"(a[3]),
                   "r"(b0), "r"(b1));
}
// accurate activations via MUFU exp (error ~1e-6; validated R8/R11-R15)
__device__ __forceinline__ float sigm_e(float x) {
    return __fdividef(1.f, 1.f + __expf(-x));
}
__device__ __forceinline__ float tanh_e(float x) {
    return 1.f - __fdividef(2.f, __expf(2.f * x) + 1.f);
}
__device__ __forceinline__ uint32_t pack_bf16(float a, float b) {
    return (uint32_t)__bfloat16_as_ushort(__float2bfloat16(a)) |
           ((uint32_t)__bfloat16_as_ushort(__float2bfloat16(b)) << 16);
}

// ===========================================================================
// Kernel 0a: split x into hi/lo bf16
// ===========================================================================
__global__ __launch_bounds__(256)
void conv_x(const float* __restrict__ x)
{
    size_t i = ((size_t)blockIdx.x * 256 + threadIdx.x) * 4;
    float4 v = *(const float4*)(x + i);
    float vv[4] = {v.x, v.y, v.z, v.w};
    unsigned short hi[4], lo[4];
#pragma unroll
    for (int j = 0; j < 4; j++) {
        __nv_bfloat16 h = __float2bfloat16(vv[j]);
        __nv_bfloat16 l = __float2bfloat16(vv[j] - __bfloat162float(h));
        hi[j] = __bfloat16_as_ushort(h);
        lo[j] = __bfloat16_as_ushort(l);
    }
    *(uint2*)((unsigned short*)g_xhi + i) = *(uint2*)hi;
    *(uint2*)((unsigned short*)g_xlo + i) = *(uint2*)lo;
}

// ===========================================================================
// Kernel 0b: split W into hi/lo bf16 (concat fwd|bwd), and combined biases
// ===========================================================================
__global__ __launch_bounds__(256)
void conv_w(const float* __restrict__ Wf, const float* __restrict__ Wb,
            const float* __restrict__ bihf, const float* __restrict__ bhhf,
            const float* __restrict__ bihb, const float* __restrict__ bhhb)
{
    size_t e0 = ((size_t)blockIdx.x * 256 + threadIdx.x) * 4;
    int row = (int)(e0 >> 9);
    int col = (int)(e0 & 511);
    const float* src = (row < GATES) ? (Wf + (size_t)row * 512 + col)
                                     : (Wb + (size_t)(row - GATES) * 512 + col);
    float4 v = *(const float4*)src;
    float vv[4] = {v.x, v.y, v.z, v.w};
    unsigned short hi[4], lo[4];
#pragma unroll
    for (int j = 0; j < 4; j++) {
        __nv_bfloat16 h = __float2bfloat16(vv[j]);
        __nv_bfloat16 l = __float2bfloat16(vv[j] - __bfloat162float(h));
        hi[j] = __bfloat16_as_ushort(h);
        lo[j] = __bfloat16_as_ushort(l);
    }
    *(uint2*)((unsigned short*)g_whi + e0) = *(uint2*)hi;
    *(uint2*)((unsigned short*)g_wlo + e0) = *(uint2*)lo;

    if (blockIdx.x == 0) {
        for (int n = threadIdx.x; n < 2048; n += 256) {
            int r = n & (GATES - 1);
            g_bsum[n] = (n < GATES) ? (bihf[r] + bhhf[r]) : (bihb[r] + bhhb[r]);
        }
    }
}

// ===========================================================================
// Kernel 1: mma.sync bf16 GEMM  C[32768,2048] = x @ Wcat^T + bsum
// R17: 512 threads / 16 warps (4 per SMSP), warp tile 32x32 — accumulators
// halve to 32 regs/thread and warp count doubles for latency hiding. Same
// 3-stage cp.async pipeline, same pitch-80 layout + fragment addressing.
// ===========================================================================
#define STG_HALF 20480                      // halves per stage (4 * 128*40)
#define GEMM_SMEM (3 * STG_HALF * 2)        // 122880 bytes

__device__ __forceinline__ void stage_load(uint32_t smbase, int st,
                                           int m0, int n0, int k0, int tid)
{
    const __nv_bfloat16* const xh = g_xhi + (size_t)m0 * 512 + k0;
    const __nv_bfloat16* const xl = g_xlo + (size_t)m0 * 512 + k0;
    const __nv_bfloat16* const wh = g_whi + (size_t)n0 * 512 + k0;
    const __nv_bfloat16* const wl = g_wlo + (size_t)n0 * 512 + k0;
    const uint32_t sbase = smbase + st * (STG_HALF * 2);
    const int row = tid >> 2;          // 0..127 (512 threads)
    const int seg = tid & 3;           // 0..3

#pragma unroll
    for (int mat = 0; mat < 4; mat++) {
        const __nv_bfloat16* src =
            (mat == 0) ? xh : (mat == 1) ? xl : (mat == 2) ? wh : wl;
        uint32_t dst = sbase + (uint32_t)(mat * 10240 + row * 80 + seg * 16);
        cp16(dst, src + (size_t)row * 512 + seg * 8);
    }
}

__global__ __launch_bounds__(512)
void lstm_gemm_mma()
{
    extern __shared__ char smg[];
    const uint32_t smbase = smem_u32(smg);
    const int tid  = threadIdx.x;
    const int lane = tid & 31;
    const int wid  = tid >> 5;              // 0..15
    const int wm = (wid & 3) * 32;          // warp m offset (4 warps in m)
    const int wn = (wid >> 2) * 32;         // warp n offset (4 warps in n)
    const int n0 = blockIdx.x * 128;        // 16 n-tiles (fast -> x reuse in L2)
    const int m0 = blockIdx.y * 128;        // 256 m-tiles

    float acc[2][4][4];
#pragma unroll
    for (int i = 0; i < 2; i++)
#pragma unroll
        for (int j = 0; j < 4; j++)
#pragma unroll
            for (int q = 0; q < 4; q++) acc[i][j][q] = 0.f;

    const uint32_t a_row = (uint32_t)(lane & 15);
    const uint32_t a_col = (uint32_t)((lane >> 4) * 8);
    const uint32_t b_row = (uint32_t)((lane & 7) + ((lane >> 4) << 3));
    const uint32_t b_col = (uint32_t)(((lane >> 3) & 1) * 8);

    stage_load(smbase, 0, m0, n0, 0, tid);  cp_commit();
    stage_load(smbase, 1, m0, n0, 32, tid); cp_commit();

    for (int c = 0; c < 16; c++) {
        if (c + 2 < 16) stage_load(smbase, (c + 2) % 3, m0, n0, (c + 2) * 32, tid);
        cp_commit();
        cp_wait<2>();
        __syncthreads();

        uint32_t sb  = smbase + (uint32_t)((c % 3) * (STG_HALF * 2));
        uint32_t sAh = sb;
        uint32_t sAl = sb + 10240;
        uint32_t sBh = sb + 20480;
        uint32_t sBl = sb + 30720;

#pragma unroll
        for (int kk = 0; kk < 2; kk++) {
            const uint32_t kb = (uint32_t)(kk * 32);

            uint32_t ah[2][4], al[2][4];
#pragma unroll
            for (int tm = 0; tm < 2; tm++) {
                uint32_t roff = (uint32_t)(wm + tm * 16) + a_row;
                uint32_t off = roff * 80 + kb + a_col * 2;
                ldm_x4(ah[tm][0], ah[tm][1], ah[tm][2], ah[tm][3], sAh + off);
                ldm_x4(al[tm][0], al[tm][1], al[tm][2], al[tm][3], sAl + off);
            }

            uint32_t b[8];
#pragma unroll
            for (int p = 0; p < 2; p++) {
                uint32_t roff = (uint32_t)(wn + p * 16) + b_row;
                uint32_t off = roff * 80 + kb + b_col * 2;
                ldm_x4(b[p * 4 + 0], b[p * 4 + 1], b[p * 4 + 2], b[p * 4 + 3],
                       sBh + off);
            }
            // hi*hi and lo*hi
#pragma unroll
            for (int tm = 0; tm < 2; tm++)
#pragma unroll
                for (int tn = 0; tn < 4; tn++) {
                    mma_bf16(acc[tm][tn], ah[tm], b[tn * 2], b[tn * 2 + 1]);
                    mma_bf16(acc[tm][tn], al[tm], b[tn * 2], b[tn * 2 + 1]);
                }
            // hi*lo
#pragma unroll
            for (int p = 0; p < 2; p++) {
                uint32_t roff = (uint32_t)(wn + p * 16) + b_row;
                uint32_t off = roff * 80 + kb + b_col * 2;
                ldm_x4(b[p * 4 + 0], b[p * 4 + 1], b[p * 4 + 2], b[p * 4 + 3],
                       sBl + off);
            }
#pragma unroll
            for (int tm = 0; tm < 2; tm++)
#pragma unroll
                for (int tn = 0; tn < 4; tn++)
                    mma_bf16(acc[tm][tn], ah[tm], b[tn * 2], b[tn * 2 + 1]);
        }
        __syncthreads();
    }

#pragma unroll
    for (int tm = 0; tm < 2; tm++) {
#pragma unroll
        for (int tn = 0; tn < 4; tn++) {
            const int n    = n0 + wn + tn * 8 + (lane & 3) * 2;
            const int dir  = n >> 10;
            const int rowg = n & (GATES - 1);
            const int gate = rowg >> 8;
            const int slc  = (rowg >> 5) & 7;
            const int j    = rowg & 31;
            float b0 = g_bsum[n];
            float b1 = g_bsum[n + 1];
#pragma unroll
            for (int rr = 0; rr < 2; rr++) {
                const int m  = m0 + wm + tm * 16 + (lane >> 2) + rr * 8;
                const int t  = m >> 6;
                const int bq = m & 63;
                size_t base = (((((size_t)dir * LQ + t) * 8 + (bq >> 3)) * 8 + slc) * 8
                               + (bq & 7)) * 128 + gate * 32 + j;
                float2 v;
                v.x = acc[tm][tn][rr * 2 + 0] + b0;
                v.y = acc[tm][tn][rr * 2 + 1] + b1;
                *(float2*)&g_xw[base] = v;
            }
        }
    }
}

// ===========================================================================
// Kernel 2: recurrence via HMMA — EXACT R15 (validated 1921 us; R16's 4-chain
// variant regressed and is reverted). Cluster of 8 CTAs, 2 chains/cluster.
// ===========================================================================
#define HPITCH   264                         // halves per h row (pad: 528B)
#define R_SH_HI  0                           // [2][16][HPITCH] bf16
#define R_SH_LO  16896                       // [2][16][HPITCH] bf16
#define R_GTP    33792                       // [2][16][132] float
#define R_XWS    50688                       // [2][2048] float
#define REC_SMEM 67072

__global__ void __cluster_dims__(8, 1, 1) __launch_bounds__(512, 1)
lstm_recurrence(const float* __restrict__ Whh_f,
                const float* __restrict__ Whh_b,
                const float* __restrict__ mask,
                float* __restrict__ out)
{
    extern __shared__ char smr[];
    float* gtp = (float*)(smr + R_GTP);      // [(kh*16+b)*132 + r]
    float* xws = (float*)(smr + R_XWS);      // [p*2048 + ab*128 + g*32 + j]

    const int tid  = threadIdx.x;
    const int lane = tid & 31;
    const int w    = tid >> 5;               // 0..15
    const int rs   = w >> 1;                 // row slab (16 rows of 128)
    const int kh   = w & 1;                  // k half (128 of 256)
    const uint32_t s = ctarank();            // cluster rank = h-slice
    const int gid = blockIdx.x >> 3;         // 0..7
    const int dir = gid >> 2;                // 0 fwd, 1 bwd
    const int bgp = gid & 3;                 // batch-group PAIR (16 batches)

    const float* Whh = dir ? Whh_b : Whh_f;

    // ---- load W_hh slice into mma A-fragments (split bf16 hi/lo), once ----
    const int r0 = 16 * rs + (lane >> 2);
    const int r1 = r0 + 8;
    const int grow0 = ((r0 >> 5) << 8) | ((int)s << 5) | (r0 & 31);
    const int grow1 = ((r1 >> 5) << 8) | ((int)s << 5) | (r1 & 31);
    const int kc = (lane & 3) * 2;

    uint32_t ahi[8][4], alo[8][4];
#pragma unroll
    for (int kt = 0; kt < 8; kt++) {
        const int kb = kh * 128 + kt * 16 + kc;
#pragma unroll
        for (int q = 0; q < 4; q++) {
            const int gr = (q & 1) ? grow1 : grow0;
            const int kk = kb + ((q >> 1) ? 8 : 0);
            float2 f = *(const float2*)&Whh[(size_t)gr * 256 + kk];
            float hx = __bfloat162float(__float2bfloat16(f.x));
            float hy = __bfloat162float(__float2bfloat16(f.y));
            ahi[kt][q] = pack_bf16(f.x, f.y);
            alo[kt][q] = pack_bf16(f.x - hx, f.y - hy);
        }
    }

    // zero phase-0 h buffers (both planes); phase 1 fully overwritten later
    {
        __nv_bfloat16* zh = (__nv_bfloat16*)(smr + R_SH_HI);
        __nv_bfloat16* zl = (__nv_bfloat16*)(smr + R_SH_LO);
        for (int idx = tid; idx < 16 * HPITCH; idx += 512) {
            zh[idx] = __float2bfloat16(0.f);
            zl[idx] = __float2bfloat16(0.f);
        }
    }
    __syncthreads();

    const uint32_t hbase  = smem_u32(smr) + R_SH_HI;
    const uint32_t lo_off = R_SH_LO - R_SH_HI;
    // B-fragment (n=16) ldmatrix addressing — same pattern as the validated GEMM
    const uint32_t b_row  = (uint32_t)((lane & 7) + ((lane >> 4) << 3));
    const uint32_t ldm_off = b_row * (HPITCH * 2)
                           + (((lane >> 3) & 1) * 16)
                           + (uint32_t)kh * 256;
    const uint32_t phase_sz = (uint32_t)(16 * HPITCH * 2);

    // activation role: ALL 512 threads, one (batch, h-index) each
    const int ab = w;                        // batch within pair-group (0..15)
    const int aj = lane;
    const int bglob_a = bgp * 16 + ab;
    const int bcol = (lane & 3) * 2;

    // cp.async role: thread (ab, g=lane>>3, grp=lane&7) fetches 16B of xW
    const int cg  = lane >> 3;               // gate 0..3
    const int cgr = lane & 7;                // 4-float group
    const float* xw_src_base = g_xw
        + ((size_t)dir * LQ * 64 + (size_t)(bgp * 2 + (ab >> 3)) * 8 + s) * 1024
        + (size_t)(ab & 7) * 128 + cg * 32 + cgr * 4;
    const uint32_t xw_dst_base = smem_u32(smr) + R_XWS
        + (uint32_t)(ab * 128 + cg * 32 + cgr * 4) * 4;

    // DSMEM group offset for this lane-group's 4 packed h elements
    const uint32_t grp_hoff = (uint32_t)(ab * (HPITCH * 2)
                                         + ((int)s * 32 + (aj & ~3)) * 2);

    float c = 0.f;

#pragma unroll 1
    for (int step = 0; step < LQ; step++) {
        const int t = dir ? (LQ - 1 - step) : step;
        const int p = step & 1;

        // ---- prefetch xW into smem stage + mask (before the cluster wait) --
        cp16(xw_dst_base + (uint32_t)p * 8192, xw_src_base + (size_t)t * 65536);
        cp_commit();
        float m = __ldg(&mask[t * BQ + bglob_a]);

        if (step > 0)
            asm volatile("barrier.cluster.wait.aligned;" ::: "memory");

        // ---- matvec: this warp's k-half, n=16 (two 8-batch tiles) ----
        float acc0[4] = {0.f, 0.f, 0.f, 0.f};
        float acc1[4] = {0.f, 0.f, 0.f, 0.f};
        const uint32_t hb = hbase + (uint32_t)p * phase_sz + ldm_off;
#pragma unroll
        for (int kt = 0; kt < 8; kt++) {
            uint32_t bh0, bh1, bh2, bh3, bl0, bl1, bl2, bl3;
            ldm_x4(bh0, bh1, bh2, bh3, hb + kt * 32);
            ldm_x4(bl0, bl1, bl2, bl3, hb + lo_off + kt * 32);
            mma_bf16(acc0, ahi[kt], bh0, bh1);
            mma_bf16(acc1, ahi[kt], bh2, bh3);
            mma_bf16(acc0, ahi[kt], bl0, bl1);
            mma_bf16(acc1, ahi[kt], bl2, bl3);
            mma_bf16(acc0, alo[kt], bh0, bh1);
            mma_bf16(acc1, alo[kt], bh2, bh3);
        }

        // ---- partial gates to smem (per k-half plane, 16 batches) ----
        gtp[(kh * 16 + bcol)     * 132 + r0] = acc0[0];
        gtp[(kh * 16 + bcol + 1) * 132 + r0] = acc0[1];
        gtp[(kh * 16 + bcol)     * 132 + r1] = acc0[2];
        gtp[(kh * 16 + bcol + 1) * 132 + r1] = acc0[3];
        gtp[(kh * 16 + 8 + bcol)     * 132 + r0] = acc1[0];
        gtp[(kh * 16 + 8 + bcol + 1) * 132 + r0] = acc1[1];
        gtp[(kh * 16 + 8 + bcol)     * 132 + r1] = acc1[2];
        gtp[(kh * 16 + 8 + bcol + 1) * 132 + r1] = acc1[3];
        cp_wait<0>();
        __syncthreads();

        // ---- activations (all 512 threads) ----
        const float* xwp = xws + p * 2048 + ab * 128;
        float gi = gtp[ab * 132 + aj]      + gtp[(16 + ab) * 132 + aj]      + xwp[aj];
        float gf = gtp[ab * 132 + 32 + aj] + gtp[(16 + ab) * 132 + 32 + aj] + xwp[32 + aj];
        float gg = gtp[ab * 132 + 64 + aj] + gtp[(16 + ab) * 132 + 64 + aj] + xwp[64 + aj];
        float go = gtp[ab * 132 + 96 + aj] + gtp[(16 + ab) * 132 + 96 + aj] + xwp[96 + aj];
        float i_ = sigm_e(gi);
        float f_ = sigm_e(gf);
        float g_ = tanh_e(gg);
        float o_ = sigm_e(go);
        c = f_ * c + i_ * g_;
        float hv = o_ * tanh_e(c);
        hv *= m;
        c  *= m;

        unsigned short hhi = __bfloat16_as_ushort(__float2bfloat16(hv));
        float hv_hi = __bfloat162float(__ushort_as_bfloat16(hhi));
        unsigned short hlo = __bfloat16_as_ushort(__float2bfloat16(hv - hv_hi));

        if (step < LQ - 1) {
            // pack 4 lanes' hi/lo into 8B words; leaders store to 8 ranks
            uint32_t vh = (uint32_t)hhi;
            uint32_t vl = (uint32_t)hlo;
            uint32_t h1 = __shfl_down_sync(0xFFFFFFFFu, vh, 1);
            uint32_t h2 = __shfl_down_sync(0xFFFFFFFFu, vh, 2);
            uint32_t h3 = __shfl_down_sync(0xFFFFFFFFu, vh, 3);
            uint32_t l1 = __shfl_down_sync(0xFFFFFFFFu, vl, 1);
            uint32_t l2 = __shfl_down_sync(0xFFFFFFFFu, vl, 2);
            uint32_t l3 = __shfl_down_sync(0xFFFFFFFFu, vl, 3);
            if ((aj & 3) == 0) {
                uint64_t hq = (uint64_t)(vh | (h1 << 16))
                            | ((uint64_t)(h2 | (h3 << 16)) << 32);
                uint64_t lq = (uint64_t)(vl | (l1 << 16))
                            | ((uint64_t)(l2 | (l3 << 16)) << 32);
                uint32_t la = hbase + (uint32_t)(p ^ 1) * phase_sz + grp_hoff;
#pragma unroll
                for (int rk = 0; rk < 8; rk++) {
                    uint32_t ra;
                    asm volatile("mapa.shared::cluster.u32 %0, %1, %2;"
                                 : "=r"(ra) : "r"(la), "r"(rk));
                    asm volatile("st.shared::cluster.b64 [%0], %1;"
                                 :: "r"(ra), "l"(hq) : "memory");
                    asm volatile("st.shared::cluster.b64 [%0], %1;"
                                 :: "r"(ra + lo_off), "l"(lq) : "memory");
                }
            }
            asm volatile("barrier.cluster.arrive.aligned;" ::: "memory");
        }

        // out[] store AFTER the broadcast/arrive — off the critical path
        out[((size_t)t * BQ + bglob_a) * (2 * HALFQ) + dir * HALFQ
            + s * 32 + aj] = hv;
    }
}

// ===========================================================================
// Launch
// Inputs (metadata order): x, mask, W_ih_f, W_hh_f, b_ih_f, b_hh_f,
//                          W_ih_b, W_hh_b, b_ih_b, b_hh_b
// Output: float32 (L, B, 2*HALF)
// ===========================================================================
extern "C" void kernel_launch(void* const* d_in, const int* in_sizes, int n_in,
                              void* d_out, int out_size)
{
    const float* x     = (const float*)d_in[0];
    const float* mask  = (const float*)d_in[1];
    const float* Wihf  = (const float*)d_in[2];
    const float* Whhf  = (const float*)d_in[3];
    const float* bihf  = (const float*)d_in[4];
    const float* bhhf  = (const float*)d_in[5];
    const float* Wihb  = (const float*)d_in[6];
    const float* Whhb  = (const float*)d_in[7];
    const float* bihb  = (const float*)d_in[8];
    const float* bhhb  = (const float*)d_in[9];
    float* out = (float*)d_out;

    // Phase 0: split-bf16 conversions + bias fold
    conv_x<<<16384, 256>>>(x);
    conv_w<<<1024, 256>>>(Wihf, Wihb, bihf, bhhf, bihb, bhhb);

    // Phase 1: tensor-core (HMMA) input projection — 512 threads / 16 warps
    cudaFuncSetAttribute(lstm_gemm_mma,
                         cudaFuncAttributeMaxDynamicSharedMemorySize, GEMM_SMEM);
    dim3 ggrid(16, 256);   // n-tiles fast -> x tile reuse in L2
    lstm_gemm_mma<<<ggrid, 512, GEMM_SMEM>>>();

    // Phase 2: recurrence — EXACT R15: 64 CTAs x 512 thr, 2 chains/cluster
    cudaFuncSetAttribute(lstm_recurrence,
                         cudaFuncAttributeMaxDynamicSharedMemorySize, REC_SMEM);
    lstm_recurrence<<<64, 512, REC_SMEM>>>(Whhf, Whhb, mask, out);
}